// round 16
// baseline (speedup 1.0000x reference)
#include <cuda_runtime.h>
#include <cuda_fp16.h>
#include <math.h>
#include <stdint.h>

// ---------------- problem constants ----------------
#define S_LEN 2048
#define NH    16
#define DH    64
#define DM    1024
#define DFF   4096
#define BATCH 2
#define ROWS  (BATCH * S_LEN)   // 4096
#define QKVSZ (BATCH * NH * S_LEN * DH)   // 4M

// ---------------- scratch ----------------
__device__ __half g_Xh [ROWS * DM];
__device__ __half g_QKVh[3 * QKVSZ];
__device__ __half g_MGh[ROWS * DM];
__device__ __half g_FFh[ROWS * DFF];
__device__ float  g_H1[ROWS * DM];
__device__ float  g_BT[NH * S_LEN];
__device__ float  g_B3[3 * DM];
__device__ __half g_WTH[12 * 1024 * 1024];  // fp16 transposed weights

// ---------------- helpers ----------------
__device__ __forceinline__ uint32_t smem_u32(const void* p) {
    uint32_t a;
    asm("{ .reg .u64 t; cvta.to.shared.u64 t, %1; cvt.u32.u64 %0, t; }" : "=r"(a) : "l"(p));
    return a;
}
__device__ __forceinline__ float ex2(float x) {
    float y;
    asm("ex2.approx.ftz.f32 %0, %1;" : "=f"(y) : "f"(x));
    return y;
}
__device__ __forceinline__ uint32_t ex2h2(uint32_t x) {
    uint32_t y;
    asm("ex2.approx.f16x2 %0, %1;" : "=r"(y) : "r"(x));
    return y;
}
__device__ __forceinline__ void ldsm4(uint32_t* r, uint32_t addr) {
    asm volatile("ldmatrix.sync.aligned.m8n8.x4.shared.b16 {%0,%1,%2,%3}, [%4];"
                 : "=r"(r[0]), "=r"(r[1]), "=r"(r[2]), "=r"(r[3]) : "r"(addr));
}
__device__ __forceinline__ void ldsm4t(uint32_t* r, uint32_t addr) {
    asm volatile("ldmatrix.sync.aligned.m8n8.x4.trans.shared.b16 {%0,%1,%2,%3}, [%4];"
                 : "=r"(r[0]), "=r"(r[1]), "=r"(r[2]), "=r"(r[3]) : "r"(addr));
}
__device__ __forceinline__ void mma_f16(float* d, const uint32_t* a, uint32_t b0, uint32_t b1) {
    asm volatile(
        "mma.sync.aligned.m16n8k16.row.col.f32.f16.f16.f32 "
        "{%0,%1,%2,%3}, {%4,%5,%6,%7}, {%8,%9}, {%0,%1,%2,%3};"
        : "+f"(d[0]), "+f"(d[1]), "+f"(d[2]), "+f"(d[3])
        : "r"(a[0]), "r"(a[1]), "r"(a[2]), "r"(a[3]), "r"(b0), "r"(b1));
}
__device__ __forceinline__ uint32_t pk2h(float a, float b) {
    __half2 h = __floats2half2_rn(a, b);
    return *reinterpret_cast<uint32_t*>(&h);
}
__device__ __forceinline__ void cpa16(uint32_t dst, const void* src) {
    asm volatile("cp.async.cg.shared.global [%0], [%1], 16;" :: "r"(dst), "l"(src));
}
#define CP_COMMIT() asm volatile("cp.async.commit_group;" ::: "memory")
#define CP_WAIT(n)  asm volatile("cp.async.wait_group %0;" :: "n"(n) : "memory")

enum { EPI_QKV3 = 0, EPI_OPROJ = 3, EPI_GELU = 4, EPI_FINAL = 5 };

// ---------------- weight transposes + prep (bias table, bias concat) in one kernel ----------------
__global__ __launch_bounds__(256) void wtrans_all(
    const float* __restrict__ wq, const float* __restrict__ wk,
    const float* __restrict__ wv, const float* __restrict__ wo,
    const float* __restrict__ w1, const float* __restrict__ w2,
    __half* __restrict__ WT,
    const float* __restrict__ rel_bias, float* __restrict__ tab,
    const float* __restrict__ bq, const float* __restrict__ bk,
    const float* __restrict__ bv, float* __restrict__ b3) {
    __shared__ float t[32][33];
    const size_t M1 = 1024 * 1024;
    int tile = blockIdx.x;
    if (tile >= 12288) {           // prep tail
        int idx = (tile - 12288) * 256 + threadIdx.x;
        if (idx < NH * S_LEN) {
            int h = idx / S_LEN;
            int d = idx % S_LEN;
            int bucket;
            if (d < 16) {
                bucket = d;
            } else {
                float ratio = logf((float)d * (1.0f / 16.0f)) / logf(8.0f);
                int large = 16 + (int)(ratio * 16.0f);
                bucket = large < 31 ? large : 31;
            }
            tab[h * S_LEN + d] = rel_bias[bucket * NH + h] * 1.44269504088896340736f;
        } else {
            int i = idx - NH * S_LEN;
            if (i < 3 * DM) {
                const float* s = (i < DM) ? bq : ((i < 2 * DM) ? bk : bv);
                b3[i] = s[i & (DM - 1)];
            }
        }
        return;
    }
    const float* W;
    __half* D;
    int K, N, lt;
    if (tile < 4096) {
        int seg = tile >> 10;
        lt = tile & 1023;
        W = (seg == 0) ? wq : (seg == 1) ? wk : (seg == 2) ? wv : wo;
        D = WT + (size_t)seg * M1;
        K = DM; N = DM;
    } else if (tile < 8192) {
        lt = tile - 4096;
        W = w1; D = WT + 4 * M1; K = DM; N = DFF;
    } else {
        lt = tile - 8192;
        W = w2; D = WT + 8 * M1; K = DFF; N = DM;
    }
    int ntile = N >> 5;
    int n0 = (lt % ntile) * 32, k0 = (lt / ntile) * 32;
    int tx = threadIdx.x & 31, ty = threadIdx.x >> 5;
#pragma unroll
    for (int j = 0; j < 32; j += 8)
        t[ty + j][tx] = W[(size_t)(k0 + ty + j) * N + n0 + tx];
    __syncthreads();
#pragma unroll
    for (int j = 0; j < 32; j += 8)
        D[(size_t)(n0 + ty + j) * K + k0 + tx] = __float2half_rn(t[tx][ty + j]);
}

// ---------------- layernorm (fp32 in, fp16 out) ----------------
__global__ __launch_bounds__(256) void ln_kernel(const float* __restrict__ x,
                                                 const float* __restrict__ g,
                                                 const float* __restrict__ bta,
                                                 __half* __restrict__ y) {
    int row = blockIdx.x;
    int t = threadIdx.x;
    const float4* xr = (const float4*)(x + (size_t)row * DM);
    float4 v = xr[t];
    float s  = v.x + v.y + v.z + v.w;
    float ss = v.x * v.x + v.y * v.y + v.z * v.z + v.w * v.w;
    __shared__ float sh_s[256], sh_q[256];
    sh_s[t] = s; sh_q[t] = ss;
    __syncthreads();
    for (int o = 128; o > 0; o >>= 1) {
        if (t < o) { sh_s[t] += sh_s[t + o]; sh_q[t] += sh_q[t + o]; }
        __syncthreads();
    }
    float mean = sh_s[0] * (1.0f / DM);
    float var  = sh_q[0] * (1.0f / DM) - mean * mean;
    float rstd = rsqrtf(var + 1e-5f);
    float4 gv = ((const float4*)g)[t];
    float4 bv = ((const float4*)bta)[t];
    __half2* yr = (__half2*)(y + (size_t)row * DM);
    yr[t * 2]     = __floats2half2_rn((v.x - mean) * rstd * gv.x + bv.x,
                                      (v.y - mean) * rstd * gv.y + bv.y);
    yr[t * 2 + 1] = __floats2half2_rn((v.z - mean) * rstd * gv.z + bv.z,
                                      (v.w - mean) * rstd * gv.w + bv.w);
}

// ---------------- fp16 mma.sync GEMM, dual-width (R15 config, unchanged) ----------------
template <int EPI, int WIDE>
__global__ __launch_bounds__(WIDE ? 512 : 256, WIDE ? 1 : 2) void hgemm(
    const __half* __restrict__ A, const __half* __restrict__ Bm,
    const float* __restrict__ bias, float* __restrict__ Cf, __half* __restrict__ Ch,
    int N, int K, int lda, int ldb, int ldc,
    const float* __restrict__ aux1, const int* __restrict__ auxm) {
    constexpr int BN = WIDE ? 256 : 128;
    constexpr uint32_t B_BYTES = WIDE ? 20480u : 10240u;
    constexpr uint32_t STAGE_B = 10240u + B_BYTES;
    extern __shared__ char hsm[];
    uint32_t base = smem_u32(hsm);
    int bn = blockIdx.x * BN;
    int bm = blockIdx.y * 128;

    int tid = threadIdx.x;
    int lane = tid & 31;
    int w = tid >> 5;
    int wm = (w & 1) * 64;
    int wn = (w >> 1) * 32;

    float acc[4][4][4];
#pragma unroll
    for (int mi = 0; mi < 4; mi++)
#pragma unroll
        for (int ni = 0; ni < 4; ni++)
#pragma unroll
            for (int r = 0; r < 4; r++) acc[mi][ni][r] = 0.0f;

    const __half *Ap, *Bp;
    uint32_t adst, bdst;
    if (WIDE) {
        int arow = tid >> 2, aseg = tid & 3;
        Ap = A + (size_t)(bm + arow) * lda + aseg * 8;
        adst = (uint32_t)(arow * 80 + aseg * 16);
        int brow = tid >> 1, bseg = tid & 1;
        Bp = Bm + (size_t)(bn + brow) * ldb + bseg * 16;
        bdst = 10240u + (uint32_t)(brow * 80 + bseg * 32);
    } else {
        int srow = tid >> 1, shalf = tid & 1;
        Ap = A + (size_t)(bm + srow) * lda + shalf * 16;
        Bp = Bm + (size_t)(bn + srow) * ldb + shalf * 16;
        adst = (uint32_t)((srow * 20 + shalf * 8) * 4);
        bdst = 10240u + adst;
    }

    uint32_t lrow = (uint32_t)((lane & 7) + ((lane >> 3) & 1) * 8);
    uint32_t lk4  = (uint32_t)((lane >> 4) * 4);
    uint32_t aoffc = ((wm + lrow) * 20 + lk4) * 4;
    uint32_t boffc = 10240u + ((wn + lrow) * 20 + lk4) * 4;

    int ntiles = K >> 5;

#define HG_STAGE(st, kt) do {                                           \
        uint32_t sb = base + (uint32_t)(st) * STAGE_B;                  \
        const __half* a_ = Ap + (kt) * 32;                              \
        const __half* b_ = Bp + (kt) * 32;                              \
        if (WIDE) {                                                     \
            cpa16(sb + adst, a_);                                       \
            cpa16(sb + bdst, b_);                                       \
            cpa16(sb + bdst + 16, b_ + 8);                              \
        } else {                                                        \
            cpa16(sb + adst, a_);      cpa16(sb + adst + 16, a_ + 8);   \
            cpa16(sb + bdst, b_);      cpa16(sb + bdst + 16, b_ + 8);   \
        }                                                               \
        CP_COMMIT();                                                    \
    } while (0)

    HG_STAGE(0, 0);
    HG_STAGE(1, 1);

    int cur = 0;
    for (int kt = 0; kt < ntiles; kt++) {
        if (kt + 1 < ntiles) { CP_WAIT(1); } else { CP_WAIT(0); }
        __syncthreads();
        if (kt + 2 < ntiles) {
            int fill = cur + 2; if (fill >= 3) fill -= 3;
            HG_STAGE(fill, kt + 2);
        }

        uint32_t sb = base + (uint32_t)cur * STAGE_B;
        uint32_t abase = sb + aoffc;
        uint32_t bbase = sb + boffc;
#pragma unroll
        for (int ks = 0; ks < 2; ks++) {
            uint32_t koff = (uint32_t)(ks * 32);
            uint32_t afr[4][4], bfr[2][4];
#pragma unroll
            for (int mi = 0; mi < 4; mi++)
                ldsm4(afr[mi], abase + (uint32_t)(mi * 16 * 80) + koff);
#pragma unroll
            for (int pi = 0; pi < 2; pi++)
                ldsm4(bfr[pi], bbase + (uint32_t)(pi * 16 * 80) + koff);
#pragma unroll
            for (int mi = 0; mi < 4; mi++)
#pragma unroll
                for (int ni = 0; ni < 4; ni++) {
                    int pi = ni >> 1, od = ni & 1;
                    mma_f16(acc[mi][ni], afr[mi], bfr[pi][od], bfr[pi][od + 2]);
                }
        }
        cur++; if (cur == 3) cur = 0;
    }

    // ---- epilogue (vectorized pair stores) ----
    int r = lane >> 2, c = lane & 3;
#pragma unroll
    for (int mi = 0; mi < 4; mi++) {
#pragma unroll
        for (int ni = 0; ni < 4; ni++) {
            int r0 = bm + wm + mi * 16 + r;
            int cn = bn + wn + ni * 8 + c * 2;
#pragma unroll
            for (int h2 = 0; h2 < 2; h2++) {
                int gm = r0 + h2 * 8;
                float v0 = acc[mi][ni][h2 * 2];
                float v1 = acc[mi][ni][h2 * 2 + 1];
                int gn = cn;
                if (EPI == EPI_QKV3) {
                    int sel = gn >> 10;
                    int col = gn & (DM - 1);
                    int b = gm >> 11, s = gm & (S_LEN - 1);
                    int h = col >> 6, dh = col & 63;
                    *(__half2*)(Ch + (size_t)sel * QKVSZ +
                                (((size_t)(b * NH + h) * S_LEN + s) << 6) + dh)
                        = __floats2half2_rn(v0 + bias[gn], v1 + bias[gn + 1]);
                } else if (EPI == EPI_OPROJ) {
                    float mk = (float)auxm[gm];
                    float2 a2 = *(const float2*)(aux1 + (size_t)gm * ldc + gn);
                    float2 o2;
                    o2.x = a2.x + (v0 + bias[gn]) * mk;
                    o2.y = a2.y + (v1 + bias[gn + 1]) * mk;
                    *(float2*)(Cf + (size_t)gm * ldc + gn) = o2;
                } else if (EPI == EPI_GELU) {
                    float u0 = v0 + bias[gn], u1 = v1 + bias[gn + 1];
                    float g0 = 0.5f * u0 * (1.0f + erff(u0 * 0.70710678118654752f));
                    float g1 = 0.5f * u1 * (1.0f + erff(u1 * 0.70710678118654752f));
                    *(__half2*)(Ch + (size_t)gm * ldc + gn) = __floats2half2_rn(g0, g1);
                } else if (EPI == EPI_FINAL) {
                    float mk = (float)auxm[gm];
                    float2 a2 = *(const float2*)(aux1 + (size_t)gm * ldc + gn);
                    float2 o2;
                    o2.x = (a2.x + v0 + bias[gn]) * mk;
                    o2.y = (a2.y + v1 + bias[gn + 1]) * mk;
                    *(float2*)(Cf + (size_t)gm * ldc + gn) = o2;
                }
            }
        }
    }
}

// ---------------- fused flash attention: 1 barrier/tile, diag-skip, 2 CTAs/SM ----------------
// smem: Qs @0 (18432) | Ks[2] @18432 (36864) | Vs[2] @55296 (36864)
//       bs[2] @92160 (2048) | ms[2] @94208 (1024)
#define FL_SMEM 95232

__global__ __launch_bounds__(256, 2) void flash_kernel(
    const __half* __restrict__ Qg, const __half* __restrict__ Kg,
    const __half* __restrict__ Vg, const float* __restrict__ bt2,
    const int* __restrict__ mask, __half* __restrict__ outMG) {
    extern __shared__ char fsm[];
    uint32_t base = smem_u32(fsm);
    uint32_t* Qs = (uint32_t*)(fsm);
    float* bsb = (float*)(fsm + 92160);    // [2][256]
    float* msb = (float*)(fsm + 94208);    // [2][128]

    int bh = blockIdx.x;
    int qt = (int)gridDim.y - 1 - blockIdx.y;      // heavy tiles first
    int b = bh >> 4, h = bh & 15;
    int q0 = qt * 128;
    const __half* Qp = Qg + (size_t)bh * S_LEN * DH;
    const __half* Kp = Kg + (size_t)bh * S_LEN * DH;
    const __half* Vp = Vg + (size_t)bh * S_LEN * DH;
    const float* btr = bt2 + h * S_LEN;
    const int* mr = mask + b * S_LEN;

    int tid = threadIdx.x, lane = tid & 31, w = tid >> 5;
    int wq0 = w * 16;
    int r = lane >> 2, cq = lane & 3;

    // stage Q once
    {
        int row = tid >> 1, hf = tid & 1;
        const uint4* src = (const uint4*)(Qp + (size_t)(q0 + row) * DH + hf * 32);
        uint32_t* d = Qs + row * 36 + hf * 16;
        ((uint4*)d)[0] = src[0]; ((uint4*)d)[1] = src[1];
        ((uint4*)d)[2] = src[2]; ((uint4*)d)[3] = src[3];
    }

    int krow = tid >> 1, khf = tid & 1;
    uint32_t sdst = (uint32_t)((krow * 36 + khf * 16) * 4);

#define FL_STAGE(buf, kt) do {                                                   \
        uint32_t kb = base + 18432u + (uint32_t)(buf) * 18432u + sdst;           \
        const __half* ks_ = Kp + (size_t)((kt) * 128 + krow) * DH + khf * 32;    \
        cpa16(kb, ks_);  cpa16(kb + 16, ks_ + 8);                                \
        cpa16(kb + 32, ks_ + 16); cpa16(kb + 48, ks_ + 24);                      \
        uint32_t vb = base + 55296u + (uint32_t)(buf) * 18432u + sdst;           \
        const __half* vs_ = Vp + (size_t)((kt) * 128 + krow) * DH + khf * 32;    \
        cpa16(vb, vs_);  cpa16(vb + 16, vs_ + 8);                                \
        cpa16(vb + 32, vs_ + 16); cpa16(vb + 48, vs_ + 24);                      \
        CP_COMMIT();                                                             \
    } while (0)

    FL_STAGE(0, 0);

    uint32_t lrow = (uint32_t)((lane & 7) + ((lane >> 3) & 1) * 8);
    uint32_t lk4  = (uint32_t)((lane >> 4) * 4);
    uint32_t aQ = base + ((wq0 + lrow) * 36 + lk4) * 4;
    uint32_t koffK = (lrow * 36 + lk4) * 4;
    uint32_t voff = (uint32_t)(((lane & 7) + ((lane >> 3) & 1) * 8) * 144 +
                               ((lane >> 4) & 1) * 16);

    float m0 = -INFINITY, m1 = -INFINITY;
    float o[8][4], lac[4];
#pragma unroll
    for (int ni = 0; ni < 8; ni++)
#pragma unroll
        for (int j = 0; j < 4; j++) o[ni][j] = 0.0f;
#pragma unroll
    for (int j = 0; j < 4; j++) lac[j] = 0.0f;

    const float cS = 0.125f * 1.44269504088896340736f;
    const uint32_t ONES2 = 0x3C003C00u;

    int buf = 0;
    for (int kt = 0; kt <= qt; kt++) {
        int k0 = kt * 128;
        int pb = kt & 1;
        float* bs = bsb + pb * 256;
        float* ms = msb + pb * 128;
        // write this tile's bias/mask slices (double-buffered; safe pre-sync:
        // same-parity readers finished before the *previous* sync)
        if (tid < 255) {
            int dd = q0 - k0 - 127 + tid;
            bs[tid] = (dd >= 0) ? btr[dd] : 0.0f;
        }
        if (tid < 128) ms[tid] = mr[k0 + tid] ? 0.0f : -INFINITY;
        CP_WAIT(0);
        __syncthreads();
        // stage next tile AFTER the sync: its target buffer was last read in
        // iteration kt-1, whose compute completed before this sync.
        if (kt + 1 <= qt) FL_STAGE(buf ^ 1, kt + 1);

        uint32_t bK = base + 18432u + (uint32_t)buf * 18432u + koffK;
        uint32_t bV = base + 55296u + (uint32_t)buf * 18432u + voff;

        bool diag = (kt == qt);

        // ---- S = Q K^T (skip fully-masked column groups on the diag tile) ----
        float s[16][4];
#pragma unroll
        for (int nt = 0; nt < 16; nt++)
#pragma unroll
            for (int j = 0; j < 4; j++) s[nt][j] = 0.0f;
#pragma unroll
        for (int ks = 0; ks < 4; ks++) {
            uint32_t af[4];
            ldsm4(af, aQ + (uint32_t)(ks * 32));
#pragma unroll
            for (int pi = 0; pi < 8; pi++) {
                if (!diag || pi <= w) {
                    uint32_t bf[4];
                    ldsm4(bf, bK + (uint32_t)(pi * 16 * 36 * 4) + (uint32_t)(ks * 32));
                    mma_f16(s[pi * 2], af, bf[0], bf[2]);
                    mma_f16(s[pi * 2 + 1], af, bf[1], bf[3]);
                }
            }
        }

        // ---- logits + masks + running max ----
        int ntmax = diag ? (2 * w + 1) : 15;
        float tmax0 = -INFINITY, tmax1 = -INFINITY;
#pragma unroll
        for (int nt = 0; nt < 16; nt++) {
            if (nt <= ntmax) {
#pragma unroll
                for (int jj = 0; jj < 2; jj++) {
                    int kc = nt * 8 + cq * 2 + jj;
                    float mk = ms[kc];
                    float v0 = s[nt][jj]     * cS + bs[127 + wq0 + r - kc] + mk;
                    float v1 = s[nt][jj + 2] * cS + bs[135 + wq0 + r - kc] + mk;
                    if (diag && kc > wq0 + r)     v0 = -INFINITY;
                    if (diag && kc > wq0 + r + 8) v1 = -INFINITY;
                    s[nt][jj] = v0; s[nt][jj + 2] = v1;
                    tmax0 = fmaxf(tmax0, v0); tmax1 = fmaxf(tmax1, v1);
                }
            }
        }
        tmax0 = fmaxf(tmax0, __shfl_xor_sync(0xffffffffu, tmax0, 1));
        tmax0 = fmaxf(tmax0, __shfl_xor_sync(0xffffffffu, tmax0, 2));
        tmax1 = fmaxf(tmax1, __shfl_xor_sync(0xffffffffu, tmax1, 1));
        tmax1 = fmaxf(tmax1, __shfl_xor_sync(0xffffffffu, tmax1, 2));
        float mn0 = fmaxf(m0, tmax0), mn1 = fmaxf(m1, tmax1);
        float mnc0 = fmaxf(mn0, -1e30f), mnc1 = fmaxf(mn1, -1e30f);
        float f0 = ex2(fmaxf(m0, -1e30f) - mnc0);
        float f1 = ex2(fmaxf(m1, -1e30f) - mnc1);
        m0 = mn0; m1 = mn1;

        // ---- P = 2^(s-m), folded in place (A-frag layout) ----
#pragma unroll
        for (int nt = 0; nt < 16; nt++) {
            if (nt <= ntmax) {
                uint32_t plo = ex2h2(pk2h(s[nt][0] - mnc0, s[nt][1] - mnc0));
                uint32_t phi = ex2h2(pk2h(s[nt][2] - mnc1, s[nt][3] - mnc1));
                s[nt][0] = __uint_as_float(plo);
                s[nt][1] = __uint_as_float(phi);
            }
        }

        // ---- rescale O and l ----
#pragma unroll
        for (int ni = 0; ni < 8; ni++) {
            o[ni][0] *= f0; o[ni][1] *= f0; o[ni][2] *= f1; o[ni][3] *= f1;
        }
        lac[0] *= f0; lac[1] *= f0; lac[2] *= f1; lac[3] *= f1;

        // ---- O += P @ V; l += P @ 1 (skip zero P groups on the diag tile) ----
#pragma unroll
        for (int t = 0; t < 8; t++) {
            if (!diag || t <= w) {
                uint32_t af[4];
                af[0] = __float_as_uint(s[2 * t][0]);
                af[1] = __float_as_uint(s[2 * t][1]);
                af[2] = __float_as_uint(s[2 * t + 1][0]);
                af[3] = __float_as_uint(s[2 * t + 1][1]);
                mma_f16(lac, af, ONES2, ONES2);
#pragma unroll
                for (int pi = 0; pi < 4; pi++) {
                    uint32_t bf[4];
                    ldsm4t(bf, bV + (uint32_t)(t * 2304) + (uint32_t)(pi * 32));
                    mma_f16(o[pi * 2], af, bf[0], bf[1]);
                    mma_f16(o[pi * 2 + 1], af, bf[2], bf[3]);
                }
            }
        }
        buf ^= 1;
    }

    // ---- finalize ----
    float l0 = lac[0], l1 = lac[2];
    float inv0 = (l0 > 0.0f) ? 1.0f / l0 : 0.0f;
    float inv1 = (l1 > 0.0f) ? 1.0f / l1 : 0.0f;
    int qrow = q0 + wq0 + r;
    size_t row0 = ((size_t)b * S_LEN + qrow) * DM + h * 64;
    size_t row1 = row0 + (size_t)8 * DM;
#pragma unroll
    for (int ni = 0; ni < 8; ni++) {
        int dh = ni * 8 + cq * 2;
        *(__half2*)(outMG + row0 + dh) = __floats2half2_rn(o[ni][0] * inv0, o[ni][1] * inv0);
        *(__half2*)(outMG + row1 + dh) = __floats2half2_rn(o[ni][2] * inv1, o[ni][3] * inv1);
    }
}

// ---------------- launch ----------------
extern "C" void kernel_launch(void* const* d_in, const int* in_sizes, int n_in,
                              void* d_out, int out_size) {
    const float* hidden = (const float*)d_in[0];
    const int*   mask   = (const int*)d_in[1];
    const float* wq = (const float*)d_in[2];  const float* bq = (const float*)d_in[3];
    const float* wk = (const float*)d_in[4];  const float* bk = (const float*)d_in[5];
    const float* wv = (const float*)d_in[6];  const float* bv = (const float*)d_in[7];
    const float* wo = (const float*)d_in[8];  const float* bo = (const float*)d_in[9];
    const float* rb = (const float*)d_in[10];
    const float* ln1g = (const float*)d_in[11]; const float* ln1b = (const float*)d_in[12];
    const float* ln2g = (const float*)d_in[13]; const float* ln2b = (const float*)d_in[14];
    const float* w1 = (const float*)d_in[15]; const float* b1 = (const float*)d_in[16];
    const float* w2 = (const float*)d_in[17]; const float* b2 = (const float*)d_in[18];
    float* out = (float*)d_out;

    __half *Xh, *QKVh, *MGh, *FFh, *WT;
    float *H1, *BT, *B3;
    cudaGetSymbolAddress((void**)&Xh,   g_Xh);
    cudaGetSymbolAddress((void**)&QKVh, g_QKVh);
    cudaGetSymbolAddress((void**)&MGh,  g_MGh);
    cudaGetSymbolAddress((void**)&FFh,  g_FFh);
    cudaGetSymbolAddress((void**)&H1,   g_H1);
    cudaGetSymbolAddress((void**)&BT,   g_BT);
    cudaGetSymbolAddress((void**)&B3,   g_B3);
    cudaGetSymbolAddress((void**)&WT,   g_WTH);

    const int HG_SMEM_W = 3 * 30720;
    const int HG_SMEM_N = 3 * 20480;
    cudaFuncSetAttribute(flash_kernel, cudaFuncAttributeMaxDynamicSharedMemorySize, FL_SMEM);
    cudaFuncSetAttribute(hgemm<EPI_QKV3, 1>,  cudaFuncAttributeMaxDynamicSharedMemorySize, HG_SMEM_W);
    cudaFuncSetAttribute(hgemm<EPI_GELU, 1>,  cudaFuncAttributeMaxDynamicSharedMemorySize, HG_SMEM_W);
    cudaFuncSetAttribute(hgemm<EPI_OPROJ, 0>, cudaFuncAttributeMaxDynamicSharedMemorySize, HG_SMEM_N);
    cudaFuncSetAttribute(hgemm<EPI_FINAL, 0>, cudaFuncAttributeMaxDynamicSharedMemorySize, HG_SMEM_N);

    const size_t M1 = 1024 * 1024;
    __half *Q = QKVh, *K = QKVh + QKVSZ, *V = QKVh + 2 * QKVSZ;

    // weight transposes + prep tail (one launch)
    int prep_blocks = (NH * S_LEN + 3 * DM + 255) / 256;
    wtrans_all<<<12288 + prep_blocks, 256>>>(wq, wk, wv, wo, w1, w2, WT,
                                             rb, BT, bq, bk, bv, B3);
    ln_kernel<<<ROWS, 256>>>(hidden, ln1g, ln1b, Xh);

    // fused QKV projection (N=3072, wide)
    dim3 gQKV(3 * DM / 256, ROWS / 128);
    hgemm<EPI_QKV3, 1><<<gQKV, 512, HG_SMEM_W>>>(Xh, WT, B3, nullptr, QKVh, 3 * DM, DM, DM, DM, 0,
                                                 nullptr, nullptr);

    // fused fp16 flash attention -> merged [B,S,D] fp16
    flash_kernel<<<dim3(BATCH * NH, S_LEN / 128), 256, FL_SMEM>>>(Q, K, V, BT, mask, MGh);

    // O projection + mask + residual (fp32 out; narrow tiles, all CTAs resident)
    dim3 gProjN(DM / 128, ROWS / 128);
    hgemm<EPI_OPROJ, 0><<<gProjN, 256, HG_SMEM_N>>>(MGh, WT + 3 * M1, bo, H1, nullptr,
                                                    DM, DM, DM, DM, DM, hidden, mask);

    ln_kernel<<<ROWS, 256>>>(H1, ln2g, ln2b, Xh);

    // FFN up + exact GELU -> fp16 (wide)
    dim3 gF1(DFF / 256, ROWS / 128);
    hgemm<EPI_GELU, 1><<<gF1, 512, HG_SMEM_W>>>(Xh, WT + 4 * M1, b1, nullptr, FFh,
                                                DFF, DM, DM, DM, DFF, nullptr, nullptr);

    // FFN down + residual + mask -> fp32 out (narrow)
    hgemm<EPI_FINAL, 0><<<gProjN, 256, HG_SMEM_N>>>(FFh, WT + 8 * M1, b2, out, nullptr,
                                                    DM, DFF, DFF, DFF, DM, H1, mask);
}

// round 17
// speedup vs baseline: 1.0139x; 1.0139x over previous
#include <cuda_runtime.h>
#include <cuda_fp16.h>
#include <math.h>
#include <stdint.h>

// ---------------- problem constants ----------------
#define S_LEN 2048
#define NH    16
#define DH    64
#define DM    1024
#define DFF   4096
#define BATCH 2
#define ROWS  (BATCH * S_LEN)   // 4096
#define QKVSZ (BATCH * NH * S_LEN * DH)   // 4M

// ---------------- scratch ----------------
__device__ __half g_Xh [ROWS * DM];
__device__ __half g_QKVh[3 * QKVSZ];
__device__ __half g_MGh[ROWS * DM];
__device__ __half g_FFh[ROWS * DFF];
__device__ float  g_H1[ROWS * DM];
__device__ float  g_BT[NH * S_LEN];
__device__ float  g_B3[3 * DM];
__device__ __half g_WTH[12 * 1024 * 1024];  // fp16 transposed weights

// ---------------- helpers ----------------
__device__ __forceinline__ uint32_t smem_u32(const void* p) {
    uint32_t a;
    asm("{ .reg .u64 t; cvta.to.shared.u64 t, %1; cvt.u32.u64 %0, t; }" : "=r"(a) : "l"(p));
    return a;
}
__device__ __forceinline__ float ex2(float x) {
    float y;
    asm("ex2.approx.ftz.f32 %0, %1;" : "=f"(y) : "f"(x));
    return y;
}
__device__ __forceinline__ uint32_t ex2h2(uint32_t x) {
    uint32_t y;
    asm("ex2.approx.f16x2 %0, %1;" : "=r"(y) : "r"(x));
    return y;
}
__device__ __forceinline__ void ldsm4(uint32_t* r, uint32_t addr) {
    asm volatile("ldmatrix.sync.aligned.m8n8.x4.shared.b16 {%0,%1,%2,%3}, [%4];"
                 : "=r"(r[0]), "=r"(r[1]), "=r"(r[2]), "=r"(r[3]) : "r"(addr));
}
__device__ __forceinline__ void ldsm4t(uint32_t* r, uint32_t addr) {
    asm volatile("ldmatrix.sync.aligned.m8n8.x4.trans.shared.b16 {%0,%1,%2,%3}, [%4];"
                 : "=r"(r[0]), "=r"(r[1]), "=r"(r[2]), "=r"(r[3]) : "r"(addr));
}
__device__ __forceinline__ void mma_f16(float* d, const uint32_t* a, uint32_t b0, uint32_t b1) {
    asm volatile(
        "mma.sync.aligned.m16n8k16.row.col.f32.f16.f16.f32 "
        "{%0,%1,%2,%3}, {%4,%5,%6,%7}, {%8,%9}, {%0,%1,%2,%3};"
        : "+f"(d[0]), "+f"(d[1]), "+f"(d[2]), "+f"(d[3])
        : "r"(a[0]), "r"(a[1]), "r"(a[2]), "r"(a[3]), "r"(b0), "r"(b1));
}
__device__ __forceinline__ uint32_t pk2h(float a, float b) {
    __half2 h = __floats2half2_rn(a, b);
    return *reinterpret_cast<uint32_t*>(&h);
}
__device__ __forceinline__ void cpa16(uint32_t dst, const void* src) {
    asm volatile("cp.async.cg.shared.global [%0], [%1], 16;" :: "r"(dst), "l"(src));
}
#define CP_COMMIT() asm volatile("cp.async.commit_group;" ::: "memory")
#define CP_WAIT(n)  asm volatile("cp.async.wait_group %0;" :: "n"(n) : "memory")

enum { EPI_QKV3 = 0, EPI_OPROJ = 3, EPI_GELU = 4, EPI_FINAL = 5 };

// ---------------- weight transposes + prep (bias table, bias concat) in one kernel ----------------
__global__ __launch_bounds__(256) void wtrans_all(
    const float* __restrict__ wq, const float* __restrict__ wk,
    const float* __restrict__ wv, const float* __restrict__ wo,
    const float* __restrict__ w1, const float* __restrict__ w2,
    __half* __restrict__ WT,
    const float* __restrict__ rel_bias, float* __restrict__ tab,
    const float* __restrict__ bq, const float* __restrict__ bk,
    const float* __restrict__ bv, float* __restrict__ b3) {
    __shared__ float t[32][33];
    const size_t M1 = 1024 * 1024;
    int tile = blockIdx.x;
    if (tile >= 12288) {           // prep tail
        int idx = (tile - 12288) * 256 + threadIdx.x;
        if (idx < NH * S_LEN) {
            int h = idx / S_LEN;
            int d = idx % S_LEN;
            int bucket;
            if (d < 16) {
                bucket = d;
            } else {
                float ratio = logf((float)d * (1.0f / 16.0f)) / logf(8.0f);
                int large = 16 + (int)(ratio * 16.0f);
                bucket = large < 31 ? large : 31;
            }
            tab[h * S_LEN + d] = rel_bias[bucket * NH + h] * 1.44269504088896340736f;
        } else {
            int i = idx - NH * S_LEN;
            if (i < 3 * DM) {
                const float* s = (i < DM) ? bq : ((i < 2 * DM) ? bk : bv);
                b3[i] = s[i & (DM - 1)];
            }
        }
        return;
    }
    const float* W;
    __half* D;
    int K, N, lt;
    if (tile < 4096) {
        int seg = tile >> 10;
        lt = tile & 1023;
        W = (seg == 0) ? wq : (seg == 1) ? wk : (seg == 2) ? wv : wo;
        D = WT + (size_t)seg * M1;
        K = DM; N = DM;
    } else if (tile < 8192) {
        lt = tile - 4096;
        W = w1; D = WT + 4 * M1; K = DM; N = DFF;
    } else {
        lt = tile - 8192;
        W = w2; D = WT + 8 * M1; K = DFF; N = DM;
    }
    int ntile = N >> 5;
    int n0 = (lt % ntile) * 32, k0 = (lt / ntile) * 32;
    int tx = threadIdx.x & 31, ty = threadIdx.x >> 5;
#pragma unroll
    for (int j = 0; j < 32; j += 8)
        t[ty + j][tx] = W[(size_t)(k0 + ty + j) * N + n0 + tx];
    __syncthreads();
#pragma unroll
    for (int j = 0; j < 32; j += 8)
        D[(size_t)(n0 + ty + j) * K + k0 + tx] = __float2half_rn(t[tx][ty + j]);
}

// ---------------- layernorm (fp32 in, fp16 out) ----------------
__global__ __launch_bounds__(256) void ln_kernel(const float* __restrict__ x,
                                                 const float* __restrict__ g,
                                                 const float* __restrict__ bta,
                                                 __half* __restrict__ y) {
    int row = blockIdx.x;
    int t = threadIdx.x;
    const float4* xr = (const float4*)(x + (size_t)row * DM);
    float4 v = xr[t];
    float s  = v.x + v.y + v.z + v.w;
    float ss = v.x * v.x + v.y * v.y + v.z * v.z + v.w * v.w;
    __shared__ float sh_s[256], sh_q[256];
    sh_s[t] = s; sh_q[t] = ss;
    __syncthreads();
    for (int o = 128; o > 0; o >>= 1) {
        if (t < o) { sh_s[t] += sh_s[t + o]; sh_q[t] += sh_q[t + o]; }
        __syncthreads();
    }
    float mean = sh_s[0] * (1.0f / DM);
    float var  = sh_q[0] * (1.0f / DM) - mean * mean;
    float rstd = rsqrtf(var + 1e-5f);
    float4 gv = ((const float4*)g)[t];
    float4 bv = ((const float4*)bta)[t];
    __half2* yr = (__half2*)(y + (size_t)row * DM);
    yr[t * 2]     = __floats2half2_rn((v.x - mean) * rstd * gv.x + bv.x,
                                      (v.y - mean) * rstd * gv.y + bv.y);
    yr[t * 2 + 1] = __floats2half2_rn((v.z - mean) * rstd * gv.z + bv.z,
                                      (v.w - mean) * rstd * gv.w + bv.w);
}

// ---------------- fp16 mma.sync GEMM, dual-width (R15 config, unchanged) ----------------
template <int EPI, int WIDE>
__global__ __launch_bounds__(WIDE ? 512 : 256, WIDE ? 1 : 2) void hgemm(
    const __half* __restrict__ A, const __half* __restrict__ Bm,
    const float* __restrict__ bias, float* __restrict__ Cf, __half* __restrict__ Ch,
    int N, int K, int lda, int ldb, int ldc,
    const float* __restrict__ aux1, const int* __restrict__ auxm) {
    constexpr int BN = WIDE ? 256 : 128;
    constexpr uint32_t B_BYTES = WIDE ? 20480u : 10240u;
    constexpr uint32_t STAGE_B = 10240u + B_BYTES;
    extern __shared__ char hsm[];
    uint32_t base = smem_u32(hsm);
    int bn = blockIdx.x * BN;
    int bm = blockIdx.y * 128;

    int tid = threadIdx.x;
    int lane = tid & 31;
    int w = tid >> 5;
    int wm = (w & 1) * 64;
    int wn = (w >> 1) * 32;

    float acc[4][4][4];
#pragma unroll
    for (int mi = 0; mi < 4; mi++)
#pragma unroll
        for (int ni = 0; ni < 4; ni++)
#pragma unroll
            for (int r = 0; r < 4; r++) acc[mi][ni][r] = 0.0f;

    const __half *Ap, *Bp;
    uint32_t adst, bdst;
    if (WIDE) {
        int arow = tid >> 2, aseg = tid & 3;
        Ap = A + (size_t)(bm + arow) * lda + aseg * 8;
        adst = (uint32_t)(arow * 80 + aseg * 16);
        int brow = tid >> 1, bseg = tid & 1;
        Bp = Bm + (size_t)(bn + brow) * ldb + bseg * 16;
        bdst = 10240u + (uint32_t)(brow * 80 + bseg * 32);
    } else {
        int srow = tid >> 1, shalf = tid & 1;
        Ap = A + (size_t)(bm + srow) * lda + shalf * 16;
        Bp = Bm + (size_t)(bn + srow) * ldb + shalf * 16;
        adst = (uint32_t)((srow * 20 + shalf * 8) * 4);
        bdst = 10240u + adst;
    }

    uint32_t lrow = (uint32_t)((lane & 7) + ((lane >> 3) & 1) * 8);
    uint32_t lk4  = (uint32_t)((lane >> 4) * 4);
    uint32_t aoffc = ((wm + lrow) * 20 + lk4) * 4;
    uint32_t boffc = 10240u + ((wn + lrow) * 20 + lk4) * 4;

    int ntiles = K >> 5;

#define HG_STAGE(st, kt) do {                                           \
        uint32_t sb = base + (uint32_t)(st) * STAGE_B;                  \
        const __half* a_ = Ap + (kt) * 32;                              \
        const __half* b_ = Bp + (kt) * 32;                              \
        if (WIDE) {                                                     \
            cpa16(sb + adst, a_);                                       \
            cpa16(sb + bdst, b_);                                       \
            cpa16(sb + bdst + 16, b_ + 8);                              \
        } else {                                                        \
            cpa16(sb + adst, a_);      cpa16(sb + adst + 16, a_ + 8);   \
            cpa16(sb + bdst, b_);      cpa16(sb + bdst + 16, b_ + 8);   \
        }                                                               \
        CP_COMMIT();                                                    \
    } while (0)

    HG_STAGE(0, 0);
    HG_STAGE(1, 1);

    int cur = 0;
    for (int kt = 0; kt < ntiles; kt++) {
        if (kt + 1 < ntiles) { CP_WAIT(1); } else { CP_WAIT(0); }
        __syncthreads();
        if (kt + 2 < ntiles) {
            int fill = cur + 2; if (fill >= 3) fill -= 3;
            HG_STAGE(fill, kt + 2);
        }

        uint32_t sb = base + (uint32_t)cur * STAGE_B;
        uint32_t abase = sb + aoffc;
        uint32_t bbase = sb + boffc;
#pragma unroll
        for (int ks = 0; ks < 2; ks++) {
            uint32_t koff = (uint32_t)(ks * 32);
            uint32_t afr[4][4], bfr[2][4];
#pragma unroll
            for (int mi = 0; mi < 4; mi++)
                ldsm4(afr[mi], abase + (uint32_t)(mi * 16 * 80) + koff);
#pragma unroll
            for (int pi = 0; pi < 2; pi++)
                ldsm4(bfr[pi], bbase + (uint32_t)(pi * 16 * 80) + koff);
#pragma unroll
            for (int mi = 0; mi < 4; mi++)
#pragma unroll
                for (int ni = 0; ni < 4; ni++) {
                    int pi = ni >> 1, od = ni & 1;
                    mma_f16(acc[mi][ni], afr[mi], bfr[pi][od], bfr[pi][od + 2]);
                }
        }
        cur++; if (cur == 3) cur = 0;
    }

    // ---- epilogue (vectorized pair stores) ----
    int r = lane >> 2, c = lane & 3;
#pragma unroll
    for (int mi = 0; mi < 4; mi++) {
#pragma unroll
        for (int ni = 0; ni < 4; ni++) {
            int r0 = bm + wm + mi * 16 + r;
            int cn = bn + wn + ni * 8 + c * 2;
#pragma unroll
            for (int h2 = 0; h2 < 2; h2++) {
                int gm = r0 + h2 * 8;
                float v0 = acc[mi][ni][h2 * 2];
                float v1 = acc[mi][ni][h2 * 2 + 1];
                int gn = cn;
                if (EPI == EPI_QKV3) {
                    int sel = gn >> 10;
                    int col = gn & (DM - 1);
                    int b = gm >> 11, s = gm & (S_LEN - 1);
                    int h = col >> 6, dh = col & 63;
                    *(__half2*)(Ch + (size_t)sel * QKVSZ +
                                (((size_t)(b * NH + h) * S_LEN + s) << 6) + dh)
                        = __floats2half2_rn(v0 + bias[gn], v1 + bias[gn + 1]);
                } else if (EPI == EPI_OPROJ) {
                    float mk = (float)auxm[gm];
                    float2 a2 = *(const float2*)(aux1 + (size_t)gm * ldc + gn);
                    float2 o2;
                    o2.x = a2.x + (v0 + bias[gn]) * mk;
                    o2.y = a2.y + (v1 + bias[gn + 1]) * mk;
                    *(float2*)(Cf + (size_t)gm * ldc + gn) = o2;
                } else if (EPI == EPI_GELU) {
                    float u0 = v0 + bias[gn], u1 = v1 + bias[gn + 1];
                    float g0 = 0.5f * u0 * (1.0f + erff(u0 * 0.70710678118654752f));
                    float g1 = 0.5f * u1 * (1.0f + erff(u1 * 0.70710678118654752f));
                    *(__half2*)(Ch + (size_t)gm * ldc + gn) = __floats2half2_rn(g0, g1);
                } else if (EPI == EPI_FINAL) {
                    float mk = (float)auxm[gm];
                    float2 a2 = *(const float2*)(aux1 + (size_t)gm * ldc + gn);
                    float2 o2;
                    o2.x = (a2.x + v0 + bias[gn]) * mk;
                    o2.y = (a2.y + v1 + bias[gn + 1]) * mk;
                    *(float2*)(Cf + (size_t)gm * ldc + gn) = o2;
                }
            }
        }
    }
}

// ---------------- fused flash attention (R15 structure + PV-only diag skip) ----------------
#define FL_SMEM 93696

__global__ __launch_bounds__(256, 2) void flash_kernel(
    const __half* __restrict__ Qg, const __half* __restrict__ Kg,
    const __half* __restrict__ Vg, const float* __restrict__ bt2,
    const int* __restrict__ mask, __half* __restrict__ outMG) {
    extern __shared__ char fsm[];
    uint32_t base = smem_u32(fsm);
    uint32_t* Qs = (uint32_t*)(fsm);
    float* bs = (float*)(fsm + 92160);
    float* ms = (float*)(fsm + 93184);

    int bh = blockIdx.x;
    int qt = (int)gridDim.y - 1 - blockIdx.y;      // heavy tiles first
    int b = bh >> 4, h = bh & 15;
    int q0 = qt * 128;
    const __half* Qp = Qg + (size_t)bh * S_LEN * DH;
    const __half* Kp = Kg + (size_t)bh * S_LEN * DH;
    const __half* Vp = Vg + (size_t)bh * S_LEN * DH;
    const float* btr = bt2 + h * S_LEN;
    const int* mr = mask + b * S_LEN;

    int tid = threadIdx.x, lane = tid & 31, w = tid >> 5;
    int wq0 = w * 16;
    int r = lane >> 2, cq = lane & 3;

    // stage Q once
    {
        int row = tid >> 1, hf = tid & 1;
        const uint4* src = (const uint4*)(Qp + (size_t)(q0 + row) * DH + hf * 32);
        uint32_t* d = Qs + row * 36 + hf * 16;
        ((uint4*)d)[0] = src[0]; ((uint4*)d)[1] = src[1];
        ((uint4*)d)[2] = src[2]; ((uint4*)d)[3] = src[3];
    }

    int krow = tid >> 1, khf = tid & 1;
    uint32_t sdst = (uint32_t)((krow * 36 + khf * 16) * 4);

#define FL_STAGE(buf, kt) do {                                                   \
        uint32_t kb = base + 18432u + (uint32_t)(buf) * 18432u + sdst;           \
        const __half* ks_ = Kp + (size_t)((kt) * 128 + krow) * DH + khf * 32;    \
        cpa16(kb, ks_);  cpa16(kb + 16, ks_ + 8);                                \
        cpa16(kb + 32, ks_ + 16); cpa16(kb + 48, ks_ + 24);                      \
        uint32_t vb = base + 55296u + (uint32_t)(buf) * 18432u + sdst;           \
        const __half* vs_ = Vp + (size_t)((kt) * 128 + krow) * DH + khf * 32;    \
        cpa16(vb, vs_);  cpa16(vb + 16, vs_ + 8);                                \
        cpa16(vb + 32, vs_ + 16); cpa16(vb + 48, vs_ + 24);                      \
        CP_COMMIT();                                                             \
    } while (0)

    FL_STAGE(0, 0);

    uint32_t lrow = (uint32_t)((lane & 7) + ((lane >> 3) & 1) * 8);
    uint32_t lk4  = (uint32_t)((lane >> 4) * 4);
    uint32_t aQ = base + ((wq0 + lrow) * 36 + lk4) * 4;
    uint32_t koffK = (lrow * 36 + lk4) * 4;
    uint32_t voff = (uint32_t)(((lane & 7) + ((lane >> 3) & 1) * 8) * 144 +
                               ((lane >> 4) & 1) * 16);

    float m0 = -INFINITY, m1 = -INFINITY;
    float o[8][4], lac[4];
#pragma unroll
    for (int ni = 0; ni < 8; ni++)
#pragma unroll
        for (int j = 0; j < 4; j++) o[ni][j] = 0.0f;
#pragma unroll
    for (int j = 0; j < 4; j++) lac[j] = 0.0f;

    const float cS = 0.125f * 1.44269504088896340736f;
    const uint32_t ONES2 = 0x3C003C00u;

    int buf = 0;
    for (int kt = 0; kt <= qt; kt++) {
        int k0 = kt * 128;
        if (kt + 1 <= qt) FL_STAGE(buf ^ 1, kt + 1);
        if (tid < 255) {
            int dd = q0 - k0 - 127 + tid;
            bs[tid] = (dd >= 0) ? btr[dd] : 0.0f;
        }
        if (tid < 128) ms[tid] = mr[k0 + tid] ? 0.0f : -INFINITY;
        if (kt + 1 <= qt) { CP_WAIT(1); } else { CP_WAIT(0); }
        __syncthreads();

        uint32_t bK = base + 18432u + (uint32_t)buf * 18432u + koffK;
        uint32_t bV = base + 55296u + (uint32_t)buf * 18432u + voff;

        // ---- S = Q K^T ----
        float s[16][4];
#pragma unroll
        for (int nt = 0; nt < 16; nt++)
#pragma unroll
            for (int j = 0; j < 4; j++) s[nt][j] = 0.0f;
#pragma unroll
        for (int ks = 0; ks < 4; ks++) {
            uint32_t af[4];
            ldsm4(af, aQ + (uint32_t)(ks * 32));
#pragma unroll
            for (int pi = 0; pi < 8; pi++) {
                uint32_t bf[4];
                ldsm4(bf, bK + (uint32_t)(pi * 16 * 36 * 4) + (uint32_t)(ks * 32));
                mma_f16(s[pi * 2], af, bf[0], bf[2]);
                mma_f16(s[pi * 2 + 1], af, bf[1], bf[3]);
            }
        }

        // ---- logits + masks + running max ----
        bool diag = (kt == qt);
        float tmax0 = -INFINITY, tmax1 = -INFINITY;
#pragma unroll
        for (int nt = 0; nt < 16; nt++) {
#pragma unroll
            for (int jj = 0; jj < 2; jj++) {
                int kc = nt * 8 + cq * 2 + jj;
                float mk = ms[kc];
                float v0 = s[nt][jj]     * cS + bs[127 + wq0 + r - kc] + mk;
                float v1 = s[nt][jj + 2] * cS + bs[135 + wq0 + r - kc] + mk;
                if (diag && kc > wq0 + r)     v0 = -INFINITY;
                if (diag && kc > wq0 + r + 8) v1 = -INFINITY;
                s[nt][jj] = v0; s[nt][jj + 2] = v1;
                tmax0 = fmaxf(tmax0, v0); tmax1 = fmaxf(tmax1, v1);
            }
        }
        tmax0 = fmaxf(tmax0, __shfl_xor_sync(0xffffffffu, tmax0, 1));
        tmax0 = fmaxf(tmax0, __shfl_xor_sync(0xffffffffu, tmax0, 2));
        tmax1 = fmaxf(tmax1, __shfl_xor_sync(0xffffffffu, tmax1, 1));
        tmax1 = fmaxf(tmax1, __shfl_xor_sync(0xffffffffu, tmax1, 2));
        float mn0 = fmaxf(m0, tmax0), mn1 = fmaxf(m1, tmax1);
        float mnc0 = fmaxf(mn0, -1e30f), mnc1 = fmaxf(mn1, -1e30f);
        float f0 = ex2(fmaxf(m0, -1e30f) - mnc0);
        float f1 = ex2(fmaxf(m1, -1e30f) - mnc1);
        m0 = mn0; m1 = mn1;

        // ---- P = 2^(s-m), folded in place (A-frag layout) ----
#pragma unroll
        for (int nt = 0; nt < 16; nt++) {
            uint32_t plo = ex2h2(pk2h(s[nt][0] - mnc0, s[nt][1] - mnc0));
            uint32_t phi = ex2h2(pk2h(s[nt][2] - mnc1, s[nt][3] - mnc1));
            s[nt][0] = __uint_as_float(plo);
            s[nt][1] = __uint_as_float(phi);
        }

        // ---- rescale O and l ----
#pragma unroll
        for (int ni = 0; ni < 8; ni++) {
            o[ni][0] *= f0; o[ni][1] *= f0; o[ni][2] *= f1; o[ni][3] *= f1;
        }
        lac[0] *= f0; lac[1] *= f0; lac[2] *= f1; lac[3] *= f1;

        // ---- O += P @ V; l += P @ 1 (diag tile: skip all-zero P groups, t > w) ----
#pragma unroll
        for (int t = 0; t < 8; t++) {
            if (!diag || t <= w) {
                uint32_t af[4];
                af[0] = __float_as_uint(s[2 * t][0]);
                af[1] = __float_as_uint(s[2 * t][1]);
                af[2] = __float_as_uint(s[2 * t + 1][0]);
                af[3] = __float_as_uint(s[2 * t + 1][1]);
                mma_f16(lac, af, ONES2, ONES2);
#pragma unroll
                for (int pi = 0; pi < 4; pi++) {
                    uint32_t bf[4];
                    ldsm4t(bf, bV + (uint32_t)(t * 2304) + (uint32_t)(pi * 32));
                    mma_f16(o[pi * 2], af, bf[0], bf[1]);
                    mma_f16(o[pi * 2 + 1], af, bf[2], bf[3]);
                }
            }
        }
        __syncthreads();
        buf ^= 1;
    }

    // ---- finalize ----
    float l0 = lac[0], l1 = lac[2];
    float inv0 = (l0 > 0.0f) ? 1.0f / l0 : 0.0f;
    float inv1 = (l1 > 0.0f) ? 1.0f / l1 : 0.0f;
    int qrow = q0 + wq0 + r;
    size_t row0 = ((size_t)b * S_LEN + qrow) * DM + h * 64;
    size_t row1 = row0 + (size_t)8 * DM;
#pragma unroll
    for (int ni = 0; ni < 8; ni++) {
        int dh = ni * 8 + cq * 2;
        *(__half2*)(outMG + row0 + dh) = __floats2half2_rn(o[ni][0] * inv0, o[ni][1] * inv0);
        *(__half2*)(outMG + row1 + dh) = __floats2half2_rn(o[ni][2] * inv1, o[ni][3] * inv1);
    }
}

// ---------------- launch ----------------
extern "C" void kernel_launch(void* const* d_in, const int* in_sizes, int n_in,
                              void* d_out, int out_size) {
    const float* hidden = (const float*)d_in[0];
    const int*   mask   = (const int*)d_in[1];
    const float* wq = (const float*)d_in[2];  const float* bq = (const float*)d_in[3];
    const float* wk = (const float*)d_in[4];  const float* bk = (const float*)d_in[5];
    const float* wv = (const float*)d_in[6];  const float* bv = (const float*)d_in[7];
    const float* wo = (const float*)d_in[8];  const float* bo = (const float*)d_in[9];
    const float* rb = (const float*)d_in[10];
    const float* ln1g = (const float*)d_in[11]; const float* ln1b = (const float*)d_in[12];
    const float* ln2g = (const float*)d_in[13]; const float* ln2b = (const float*)d_in[14];
    const float* w1 = (const float*)d_in[15]; const float* b1 = (const float*)d_in[16];
    const float* w2 = (const float*)d_in[17]; const float* b2 = (const float*)d_in[18];
    float* out = (float*)d_out;

    __half *Xh, *QKVh, *MGh, *FFh, *WT;
    float *H1, *BT, *B3;
    cudaGetSymbolAddress((void**)&Xh,   g_Xh);
    cudaGetSymbolAddress((void**)&QKVh, g_QKVh);
    cudaGetSymbolAddress((void**)&MGh,  g_MGh);
    cudaGetSymbolAddress((void**)&FFh,  g_FFh);
    cudaGetSymbolAddress((void**)&H1,   g_H1);
    cudaGetSymbolAddress((void**)&BT,   g_BT);
    cudaGetSymbolAddress((void**)&B3,   g_B3);
    cudaGetSymbolAddress((void**)&WT,   g_WTH);

    const int HG_SMEM_W = 3 * 30720;
    const int HG_SMEM_N = 3 * 20480;
    cudaFuncSetAttribute(flash_kernel, cudaFuncAttributeMaxDynamicSharedMemorySize, FL_SMEM);
    cudaFuncSetAttribute(hgemm<EPI_QKV3, 1>,  cudaFuncAttributeMaxDynamicSharedMemorySize, HG_SMEM_W);
    cudaFuncSetAttribute(hgemm<EPI_GELU, 1>,  cudaFuncAttributeMaxDynamicSharedMemorySize, HG_SMEM_W);
    cudaFuncSetAttribute(hgemm<EPI_OPROJ, 0>, cudaFuncAttributeMaxDynamicSharedMemorySize, HG_SMEM_N);
    cudaFuncSetAttribute(hgemm<EPI_FINAL, 0>, cudaFuncAttributeMaxDynamicSharedMemorySize, HG_SMEM_N);

    const size_t M1 = 1024 * 1024;
    __half *Q = QKVh, *K = QKVh + QKVSZ, *V = QKVh + 2 * QKVSZ;

    // weight transposes + prep tail (one launch)
    int prep_blocks = (NH * S_LEN + 3 * DM + 255) / 256;
    wtrans_all<<<12288 + prep_blocks, 256>>>(wq, wk, wv, wo, w1, w2, WT,
                                             rb, BT, bq, bk, bv, B3);
    ln_kernel<<<ROWS, 256>>>(hidden, ln1g, ln1b, Xh);

    // fused QKV projection (N=3072, wide)
    dim3 gQKV(3 * DM / 256, ROWS / 128);
    hgemm<EPI_QKV3, 1><<<gQKV, 512, HG_SMEM_W>>>(Xh, WT, B3, nullptr, QKVh, 3 * DM, DM, DM, DM, 0,
                                                 nullptr, nullptr);

    // fused fp16 flash attention -> merged [B,S,D] fp16
    flash_kernel<<<dim3(BATCH * NH, S_LEN / 128), 256, FL_SMEM>>>(Q, K, V, BT, mask, MGh);

    // O projection + mask + residual (fp32 out; narrow tiles, all CTAs resident)
    dim3 gProjN(DM / 128, ROWS / 128);
    hgemm<EPI_OPROJ, 0><<<gProjN, 256, HG_SMEM_N>>>(MGh, WT + 3 * M1, bo, H1, nullptr,
                                                    DM, DM, DM, DM, DM, hidden, mask);

    ln_kernel<<<ROWS, 256>>>(H1, ln2g, ln2b, Xh);

    // FFN up + exact GELU -> fp16 (wide)
    dim3 gF1(DFF / 256, ROWS / 128);
    hgemm<EPI_GELU, 1><<<gF1, 512, HG_SMEM_W>>>(Xh, WT + 4 * M1, b1, nullptr, FFh,
                                                DFF, DM, DM, DM, DFF, nullptr, nullptr);

    // FFN down + residual + mask -> fp32 out (narrow)
    hgemm<EPI_FINAL, 0><<<gProjN, 256, HG_SMEM_N>>>(FFh, WT + 8 * M1, b2, out, nullptr,
                                                    DM, DFF, DFF, DFF, DM, H1, mask);
}